// round 9
// baseline (speedup 1.0000x reference)
#include <cuda_runtime.h>
#include <math.h>

#define B_     4
#define N_TOK  8192
#define DIM_   512
#define H_     8
#define D_     64
#define M_     256
#define L_     32
#define BH     32
#define INNER3 1536
#define KS     33

// ---------------- scratch (device globals; no allocation allowed) ----------------
__device__ float g_q[BH * N_TOK * D_];
__device__ float g_k[BH * N_TOK * D_];
__device__ float g_v[BH * N_TOK * D_];
__device__ float g_qland[BH * M_ * D_];
__device__ float g_kland[BH * M_ * D_];
__device__ float g_attn2[BH * M_ * M_];
__device__ float g_zA[BH * M_ * M_];
__device__ float g_zB[BH * M_ * M_];
__device__ float g_xz[BH * M_ * M_];
__device__ float g_t1[BH * M_ * M_];
__device__ float g_t2[BH * M_ * M_];
__device__ float g_sim[67108864];          // [bh, 256, 8192] reused for sim3 then sim1
__device__ float g_a3v[BH * M_ * D_];
__device__ float g_w[BH * M_ * D_];
__device__ float g_outh[B_ * N_TOK * H_ * D_];   // [b, n, h, d]
__device__ unsigned g_scal[2];

// ---------------- zero-init (avoid memset nodes) ----------------
__global__ void k_zero(float* a3v, unsigned* scal) {
    int idx = blockIdx.x * 256 + threadIdx.x;
    if (idx < BH * M_ * D_) a3v[idx] = 0.f;
    if (idx < 2) scal[idx] = 0u;
}

// ---------------- QKV GEMM: [32768,512] @ [512,1536], scatter to q/k/v [b,h,n,d] ----------------
__global__ __launch_bounds__(256, 2)
void k_qkv(const float* __restrict__ X, const float* __restrict__ W,
           float* __restrict__ q, float* __restrict__ k, float* __restrict__ v) {
    __shared__ float As[8][132];
    __shared__ float Bs[8][128];
    const int tid  = threadIdx.x;
    const int row0 = blockIdx.y * 128;
    const int col0 = blockIdx.x * 128;
    const int tx = tid & 15, ty = tid >> 4;
    float acc[8][8];
#pragma unroll
    for (int i = 0; i < 8; i++)
#pragma unroll
        for (int j = 0; j < 8; j++) acc[i][j] = 0.f;

    const int a_row = tid >> 1, a_k = (tid & 1) * 4;
    const int b_k = tid >> 5, b_col = (tid & 31) * 4;
    const float* Ap = X + (row0 + a_row) * DIM_ + a_k;
    const float* Bp = W + b_k * INNER3 + col0 + b_col;

    for (int k0 = 0; k0 < DIM_; k0 += 8) {
        float4 a4 = *(const float4*)Ap; Ap += 8;
        float4 b4 = *(const float4*)Bp; Bp += 8 * INNER3;
        __syncthreads();
        As[a_k + 0][a_row] = a4.x; As[a_k + 1][a_row] = a4.y;
        As[a_k + 2][a_row] = a4.z; As[a_k + 3][a_row] = a4.w;
        *(float4*)&Bs[b_k][b_col] = b4;
        __syncthreads();
#pragma unroll
        for (int kk = 0; kk < 8; kk++) {
            float a[8], b[8];
#pragma unroll
            for (int i = 0; i < 8; i++) a[i] = As[kk][ty * 8 + i];
#pragma unroll
            for (int j = 0; j < 8; j++) b[j] = Bs[kk][tx * 8 + j];
#pragma unroll
            for (int i = 0; i < 8; i++)
#pragma unroll
                for (int j = 0; j < 8; j++) acc[i][j] = fmaf(a[i], b[j], acc[i][j]);
        }
    }
#pragma unroll
    for (int i = 0; i < 8; i++) {
        int r = row0 + ty * 8 + i;
        int bb = r >> 13, n = r & (N_TOK - 1);
#pragma unroll
        for (int j = 0; j < 8; j++) {
            int c = col0 + tx * 8 + j;
            int sect = c >> 9, cc = c & 511;
            int h = cc >> 6, d = cc & 63;
            int o = ((bb * H_ + h) * N_TOK + n) * D_ + d;
            float val = acc[i][j];
            if (sect == 0)      q[o] = val * 0.125f;   // dh^-0.5
            else if (sect == 1) k[o] = val;
            else                v[o] = val;
        }
    }
}

// ---------------- landmarks: mean over groups of 32 tokens ----------------
__global__ void k_land(const float* __restrict__ q, const float* __restrict__ k,
                       float* __restrict__ ql, float* __restrict__ kl) {
    int idx = blockIdx.x * 256 + threadIdx.x;
    if (idx >= BH * M_ * D_) return;
    int d = idx & 63, m = (idx >> 6) & 255, bh = idx >> 14;
    const float* qp = q + (bh * N_TOK + m * L_) * D_ + d;
    const float* kp = k + (bh * N_TOK + m * L_) * D_ + d;
    float sq = 0.f, sk = 0.f;
#pragma unroll
    for (int j = 0; j < L_; j++) { sq += qp[j * D_]; sk += kp[j * D_]; }
    ql[idx] = sq * (1.f / L_);
    kl[idx] = sk * (1.f / L_);
}

// ---------------- sim2 + row softmax -> attn2 ----------------
__global__ void k_sim2(const float* __restrict__ ql, const float* __restrict__ kl,
                       float* __restrict__ a2) {
    int i = blockIdx.x, bh = blockIdx.y, tid = threadIdx.x;
    __shared__ float qrow[64];
    __shared__ float red[256];
    if (tid < 64) qrow[tid] = ql[(bh * M_ + i) * D_ + tid];
    __syncthreads();
    const float* kr = kl + (bh * M_ + tid) * D_;
    float s = 0.f;
#pragma unroll
    for (int d = 0; d < 64; d++) s = fmaf(qrow[d], kr[d], s);
    red[tid] = s; __syncthreads();
    for (int o = 128; o; o >>= 1) { if (tid < o) red[tid] = fmaxf(red[tid], red[tid + o]); __syncthreads(); }
    float mx = red[0]; __syncthreads();
    float e = expf(s - mx);
    red[tid] = e; __syncthreads();
    for (int o = 128; o; o >>= 1) { if (tid < o) red[tid] += red[tid + o]; __syncthreads(); }
    a2[(bh * M_ + i) * M_ + tid] = e / red[0];
}

// ---------------- global max of row/col abs-sums of attn2 (all entries > 0) ----------------
__global__ void k_scal(const float* __restrict__ a2, unsigned* scal) {
    int bh = blockIdx.x, tid = threadIdx.x;
    const float* base = a2 + bh * M_ * M_;
    float cs = 0.f;                       // sums over axis -2
    for (int i = 0; i < M_; i++) cs += base[i * M_ + tid];
    float rs = 0.f;                       // sums over axis -1
    const float* rp = base + tid * M_;
    for (int j = 0; j < M_; j++) rs += rp[j];
    __shared__ float red[256];
    red[tid] = cs; __syncthreads();
    for (int o = 128; o; o >>= 1) { if (tid < o) red[tid] = fmaxf(red[tid], red[tid + o]); __syncthreads(); }
    if (tid == 0) atomicMax(&scal[0], __float_as_uint(red[0]));
    __syncthreads();
    red[tid] = rs; __syncthreads();
    for (int o = 128; o; o >>= 1) { if (tid < o) red[tid] = fmaxf(red[tid], red[tid + o]); __syncthreads(); }
    if (tid == 0) atomicMax(&scal[1], __float_as_uint(red[0]));
}

// ---------------- z0 = attn2^T / (max_rowsum * max_colsum) ----------------
__global__ void k_zinit(const float* __restrict__ a2, float* __restrict__ z, const unsigned* scal) {
    int idx = blockIdx.x * 256 + threadIdx.x;
    if (idx >= BH * M_ * M_) return;
    float sc = 1.f / (__uint_as_float(scal[0]) * __uint_as_float(scal[1]));
    int bh = idx >> 16, r = (idx >> 8) & 255, c = idx & 255;
    z[idx] = a2[(bh << 16) | (c << 8) | r] * sc;
}

// ---------------- generic batched 64x64-tile NN GEMM ----------------
// MODE 0: C = s*(c*A - A@B)   (pinv forms; c=0,s=-1 gives plain A@B)
// MODE 1: C = A@B
// MODE 2: split-K, atomicAdd(C, A@B)   (blockIdx.z = bh*8 + kchunk)
// MODE 3: C = A@B scattered to g_outh layout [b,n,h,d] (batch = bh)
template <int MODE>
__global__ __launch_bounds__(256)
void k_gemm64(const float* __restrict__ A, const float* __restrict__ B, float* __restrict__ C,
              int lda, int ldb, int ldc, int Ksz,
              long long sA, long long sB, long long sC, float cterm, float sterm) {
    int bz = blockIdx.z;
    int batch = (MODE == 2) ? (bz >> 3) : bz;
    int kc    = (MODE == 2) ? (bz & 7) : 0;
    A += (long long)batch * sA; B += (long long)batch * sB; C += (long long)batch * sC;
    int m0 = blockIdx.y * 64, n0 = blockIdx.x * 64;
    __shared__ float As[16][68];
    __shared__ float Bs[16][64];
    int tid = threadIdx.x;
    int a_m = tid >> 2, a_k = (tid & 3) * 4;
    int b_k = tid >> 4, b_n = (tid & 15) * 4;
    int tm = tid >> 4, tn = tid & 15;
    float acc[4][4];
#pragma unroll
    for (int i = 0; i < 4; i++)
#pragma unroll
        for (int j = 0; j < 4; j++) acc[i][j] = 0.f;

    int koff = kc * Ksz;
    const float* Ap = A + (m0 + a_m) * lda + koff + a_k;
    const float* Bp = B + (long long)(koff + b_k) * ldb + n0 + b_n;
    for (int k0 = 0; k0 < Ksz; k0 += 16) {
        float4 a4 = *(const float4*)Ap; Ap += 16;
        float4 b4 = *(const float4*)Bp; Bp += 16 * (long long)ldb;
        __syncthreads();
        As[a_k + 0][a_m] = a4.x; As[a_k + 1][a_m] = a4.y;
        As[a_k + 2][a_m] = a4.z; As[a_k + 3][a_m] = a4.w;
        *(float4*)&Bs[b_k][b_n] = b4;
        __syncthreads();
#pragma unroll
        for (int kk = 0; kk < 16; kk++) {
            float4 a = *(const float4*)&As[kk][tm * 4];
            float4 b = *(const float4*)&Bs[kk][tn * 4];
            acc[0][0] = fmaf(a.x, b.x, acc[0][0]); acc[0][1] = fmaf(a.x, b.y, acc[0][1]);
            acc[0][2] = fmaf(a.x, b.z, acc[0][2]); acc[0][3] = fmaf(a.x, b.w, acc[0][3]);
            acc[1][0] = fmaf(a.y, b.x, acc[1][0]); acc[1][1] = fmaf(a.y, b.y, acc[1][1]);
            acc[1][2] = fmaf(a.y, b.z, acc[1][2]); acc[1][3] = fmaf(a.y, b.w, acc[1][3]);
            acc[2][0] = fmaf(a.z, b.x, acc[2][0]); acc[2][1] = fmaf(a.z, b.y, acc[2][1]);
            acc[2][2] = fmaf(a.z, b.z, acc[2][2]); acc[2][3] = fmaf(a.z, b.w, acc[2][3]);
            acc[3][0] = fmaf(a.w, b.x, acc[3][0]); acc[3][1] = fmaf(a.w, b.y, acc[3][1]);
            acc[3][2] = fmaf(a.w, b.z, acc[3][2]); acc[3][3] = fmaf(a.w, b.w, acc[3][3]);
        }
    }
#pragma unroll
    for (int i = 0; i < 4; i++) {
        int row = m0 + tm * 4 + i;
#pragma unroll
        for (int j = 0; j < 4; j++) {
            int col = n0 + tn * 4 + j;
            if (MODE == 0) {
                float ae = A[row * lda + col];
                C[row * ldc + col] = sterm * (cterm * ae - acc[i][j]);
            } else if (MODE == 1) {
                C[row * ldc + col] = acc[i][j];
            } else if (MODE == 2) {
                atomicAdd(&C[row * ldc + col], acc[i][j]);
            } else {
                int b = batch >> 3, h = batch & 7;
                C[((b * N_TOK + row) * H_ + h) * D_ + col] = acc[i][j];
            }
        }
    }
}

// ---------------- NT GEMM, K=64 resident: C[M,N] = A[M,64] . B[N,64]^T ----------------
__global__ __launch_bounds__(256)
void k_nt64(const float* __restrict__ A, const float* __restrict__ B, float* __restrict__ C,
            int Nc, long long sA, long long sB, long long sC) {
    int bh = blockIdx.z;
    A += (long long)bh * sA; B += (long long)bh * sB; C += (long long)bh * sC;
    int n0 = blockIdx.x * 64, m0 = blockIdx.y * 64;
    __shared__ float As[64][68];
    __shared__ float Bs[64][68];
    int tid = threadIdx.x;
    int lm = tid >> 2, lk = (tid & 3) * 4;
    const float* Ap = A + (m0 + lm) * 64 + lk;
    const float* Bp = B + (n0 + lm) * 64 + lk;
#pragma unroll
    for (int qq = 0; qq < 4; qq++) {
        float4 a4 = *(const float4*)(Ap + qq * 16);
        int kb = lk + 16 * qq;
        As[kb + 0][lm] = a4.x; As[kb + 1][lm] = a4.y; As[kb + 2][lm] = a4.z; As[kb + 3][lm] = a4.w;
        float4 b4 = *(const float4*)(Bp + qq * 16);
        Bs[kb + 0][lm] = b4.x; Bs[kb + 1][lm] = b4.y; Bs[kb + 2][lm] = b4.z; Bs[kb + 3][lm] = b4.w;
    }
    __syncthreads();
    int tm = tid >> 4, tn = tid & 15;
    float acc[4][4];
#pragma unroll
    for (int i = 0; i < 4; i++)
#pragma unroll
        for (int j = 0; j < 4; j++) acc[i][j] = 0.f;
#pragma unroll 8
    for (int kk = 0; kk < 64; kk++) {
        float4 a = *(const float4*)&As[kk][tm * 4];
        float4 b = *(const float4*)&Bs[kk][tn * 4];
        acc[0][0] = fmaf(a.x, b.x, acc[0][0]); acc[0][1] = fmaf(a.x, b.y, acc[0][1]);
        acc[0][2] = fmaf(a.x, b.z, acc[0][2]); acc[0][3] = fmaf(a.x, b.w, acc[0][3]);
        acc[1][0] = fmaf(a.y, b.x, acc[1][0]); acc[1][1] = fmaf(a.y, b.y, acc[1][1]);
        acc[1][2] = fmaf(a.y, b.z, acc[1][2]); acc[1][3] = fmaf(a.y, b.w, acc[1][3]);
        acc[2][0] = fmaf(a.z, b.x, acc[2][0]); acc[2][1] = fmaf(a.z, b.y, acc[2][1]);
        acc[2][2] = fmaf(a.z, b.z, acc[2][2]); acc[2][3] = fmaf(a.z, b.w, acc[2][3]);
        acc[3][0] = fmaf(a.w, b.x, acc[3][0]); acc[3][1] = fmaf(a.w, b.y, acc[3][1]);
        acc[3][2] = fmaf(a.w, b.z, acc[3][2]); acc[3][3] = fmaf(a.w, b.w, acc[3][3]);
    }
#pragma unroll
    for (int i = 0; i < 4; i++)
#pragma unroll
        for (int j = 0; j < 4; j++)
            C[(m0 + tm * 4 + i) * Nc + n0 + tn * 4 + j] = acc[i][j];
}

// ---------------- softmax over rows of length 8192 (single pass, regs) ----------------
__global__ void k_softmax_wide(float* __restrict__ data) {
    float* row = data + (size_t)blockIdx.x * N_TOK;
    int t = threadIdx.x;
    float v[32];
    float m = -1e30f;
#pragma unroll
    for (int i = 0; i < 32; i++) { v[i] = row[t + 256 * i]; m = fmaxf(m, v[i]); }
    __shared__ float red[256];
    red[t] = m; __syncthreads();
    for (int o = 128; o; o >>= 1) { if (t < o) red[t] = fmaxf(red[t], red[t + o]); __syncthreads(); }
    m = red[0]; __syncthreads();
    float s = 0.f;
#pragma unroll
    for (int i = 0; i < 32; i++) { v[i] = expf(v[i] - m); s += v[i]; }
    red[t] = s; __syncthreads();
    for (int o = 128; o; o >>= 1) { if (t < o) red[t] += red[t + o]; __syncthreads(); }
    float r = 1.f / red[0];
#pragma unroll
    for (int i = 0; i < 32; i++) row[t + 256 * i] = v[i] * r;
}

// ---------------- softmax over rows of length 256 (warp per row, 8 rows/CTA) ----------------
__global__ void k_softmax8(float* __restrict__ data) {
    int warp = threadIdx.x >> 5, lane = threadIdx.x & 31;
    float* row = data + ((size_t)blockIdx.x * 8 + warp) * M_;
    float v[8];
    float m = -1e30f;
#pragma unroll
    for (int i = 0; i < 8; i++) { v[i] = row[lane + 32 * i]; m = fmaxf(m, v[i]); }
#pragma unroll
    for (int o = 16; o; o >>= 1) m = fmaxf(m, __shfl_xor_sync(0xffffffffu, m, o));
    float s = 0.f;
#pragma unroll
    for (int i = 0; i < 8; i++) { v[i] = expf(v[i] - m); s += v[i]; }
#pragma unroll
    for (int o = 16; o; o >>= 1) s += __shfl_xor_sync(0xffffffffu, s, o);
    float r = 1.f / s;
#pragma unroll
    for (int i = 0; i < 8; i++) row[lane + 32 * i] = v[i] * r;
}

// ---------------- depthwise residual conv over sequence axis, += into g_outh ----------------
__global__ void k_conv(const float* __restrict__ v, const float* __restrict__ wres,
                       float* __restrict__ oh) {
    int n0 = blockIdx.x * 64, bh = blockIdx.y, tid = threadIdx.x;
    int b = bh >> 3, h = bh & 7;
    __shared__ float vs[96][64];
    __shared__ float ws[KS];
    if (tid < KS) ws[tid] = wres[h * KS + tid];
    for (int l = tid; l < 96 * 64; l += 256) {
        int row = l >> 6, d = l & 63;
        int n = n0 + row - 16;
        vs[row][d] = (n >= 0 && n < N_TOK) ? v[(bh * N_TOK + n) * D_ + d] : 0.f;
    }
    __syncthreads();
    for (int o = tid; o < 64 * 64; o += 256) {
        int r = o >> 6, d = o & 63;
        float acc = 0.f;
#pragma unroll
        for (int t = 0; t < KS; t++) acc = fmaf(ws[t], vs[r + t][d], acc);
        int idx = ((b * N_TOK + n0 + r) * H_ + h) * D_ + d;
        oh[idx] += acc;
    }
}

// ---------------- final projection: [32768,512] @ [512,512] + bias -> d_out ----------------
__global__ __launch_bounds__(256, 2)
void k_final(const float* __restrict__ A, const float* __restrict__ W,
             const float* __restrict__ bias, float* __restrict__ C) {
    __shared__ float As[8][132];
    __shared__ float Bs[8][128];
    const int tid = threadIdx.x;
    const int row0 = blockIdx.y * 128;
    const int col0 = blockIdx.x * 128;
    const int tx = tid & 15, ty = tid >> 4;
    float acc[8][8];
#pragma unroll
    for (int i = 0; i < 8; i++)
#pragma unroll
        for (int j = 0; j < 8; j++) acc[i][j] = 0.f;
    const int a_row = tid >> 1, a_k = (tid & 1) * 4;
    const int b_k = tid >> 5, b_col = (tid & 31) * 4;
    const float* Ap = A + (row0 + a_row) * DIM_ + a_k;
    const float* Bp = W + b_k * DIM_ + col0 + b_col;
    for (int k0 = 0; k0 < DIM_; k0 += 8) {
        float4 a4 = *(const float4*)Ap; Ap += 8;
        float4 b4 = *(const float4*)Bp; Bp += 8 * DIM_;
        __syncthreads();
        As[a_k + 0][a_row] = a4.x; As[a_k + 1][a_row] = a4.y;
        As[a_k + 2][a_row] = a4.z; As[a_k + 3][a_row] = a4.w;
        *(float4*)&Bs[b_k][b_col] = b4;
        __syncthreads();
#pragma unroll
        for (int kk = 0; kk < 8; kk++) {
            float a[8], b[8];
#pragma unroll
            for (int i = 0; i < 8; i++) a[i] = As[kk][ty * 8 + i];
#pragma unroll
            for (int j = 0; j < 8; j++) b[j] = Bs[kk][tx * 8 + j];
#pragma unroll
            for (int i = 0; i < 8; i++)
#pragma unroll
                for (int j = 0; j < 8; j++) acc[i][j] = fmaf(a[i], b[j], acc[i][j]);
        }
    }
#pragma unroll
    for (int i = 0; i < 8; i++) {
        int r = row0 + ty * 8 + i;
#pragma unroll
        for (int j = 0; j < 8; j++) {
            int c = col0 + tx * 8 + j;
            C[(size_t)r * DIM_ + c] = acc[i][j] + bias[c];
        }
    }
}

// ---------------- driver ----------------
extern "C" void kernel_launch(void* const* d_in, const int* in_sizes, int n_in,
                              void* d_out, int out_size) {
    const float* x     = (const float*)d_in[0];
    const float* w_qkv = (const float*)d_in[1];
    const float* w_out = (const float*)d_in[2];
    const float* b_out = (const float*)d_in[3];
    const float* w_res = (const float*)d_in[4];
    float* out = (float*)d_out;

    float *q, *k, *v, *ql, *kl, *a2, *zA, *zB, *xz, *t1, *t2, *sim, *a3v, *wm, *oh;
    unsigned* scal;
    cudaGetSymbolAddress((void**)&q, g_q);
    cudaGetSymbolAddress((void**)&k, g_k);
    cudaGetSymbolAddress((void**)&v, g_v);
    cudaGetSymbolAddress((void**)&ql, g_qland);
    cudaGetSymbolAddress((void**)&kl, g_kland);
    cudaGetSymbolAddress((void**)&a2, g_attn2);
    cudaGetSymbolAddress((void**)&zA, g_zA);
    cudaGetSymbolAddress((void**)&zB, g_zB);
    cudaGetSymbolAddress((void**)&xz, g_xz);
    cudaGetSymbolAddress((void**)&t1, g_t1);
    cudaGetSymbolAddress((void**)&t2, g_t2);
    cudaGetSymbolAddress((void**)&sim, g_sim);
    cudaGetSymbolAddress((void**)&a3v, g_a3v);
    cudaGetSymbolAddress((void**)&wm, g_w);
    cudaGetSymbolAddress((void**)&oh, g_outh);
    cudaGetSymbolAddress((void**)&scal, g_scal);

    const long long MM = (long long)M_ * M_;        // 65536
    const long long MD = (long long)M_ * D_;        // 16384
    const long long ND = (long long)N_TOK * D_;     // 524288
    const long long MN = (long long)M_ * N_TOK;     // 2097152

    k_zero<<<(BH * M_ * D_ + 255) / 256, 256>>>(a3v, scal);

    // qkv projection + head split + q scale
    k_qkv<<<dim3(12, 256), 256>>>(x, w_qkv, q, k, v);
    // landmarks
    k_land<<<(BH * M_ * D_ + 255) / 256, 256>>>(q, k, ql, kl);
    // attn2 = softmax(q_land . k_land^T)
    k_sim2<<<dim3(M_, BH), 256>>>(ql, kl, a2);
    k_scal<<<BH, 256>>>(a2, scal);
    k_zinit<<<(BH * M_ * M_ + 255) / 256, 256>>>(a2, zA, scal);

    // Newton–Schulz pinv, 6 iterations, ping-pong z
    float* zin = zA; float* zout = zB;
    for (int it = 0; it < 6; it++) {
        k_gemm64<0><<<dim3(4, 4, BH), 256>>>(a2, zin, xz, M_, M_, M_, M_, MM, MM, MM, 0.f, -1.f);
        k_gemm64<0><<<dim3(4, 4, BH), 256>>>(xz, xz, t1, M_, M_, M_, M_, MM, MM, MM, 7.f, 1.f);
        k_gemm64<0><<<dim3(4, 4, BH), 256>>>(xz, t1, t2, M_, M_, M_, M_, MM, MM, MM, 15.f, 1.f);
        k_gemm64<0><<<dim3(4, 4, BH), 256>>>(zin, t2, zout, M_, M_, M_, M_, MM, MM, MM, 13.f, 0.25f);
        float* tmp = zin; zin = zout; zout = tmp;
    }
    // zin now holds attn2_inv

    // attn3 = softmax(q_land . k^T)  [bh,256,8192], then attn3 @ v (split-K=8)
    k_nt64<<<dim3(N_TOK / 64, M_ / 64, BH), 256>>>(ql, k, sim, N_TOK, MD, ND, MN);
    k_softmax_wide<<<BH * M_, 256>>>(sim);
    k_gemm64<2><<<dim3(1, 4, BH * 8), 256>>>(sim, v, a3v, N_TOK, D_, D_, 1024, MN, ND, MD, 0.f, 0.f);

    // W = attn2_inv @ (attn3 @ v)
    k_gemm64<1><<<dim3(1, 4, BH), 256>>>(zin, a3v, wm, M_, D_, D_, M_, MM, MD, MD, 0.f, 0.f);

    // attn1 = softmax(q . k_land^T)  [bh,8192,256], then out = attn1 @ W  -> [b,n,h,d]
    k_nt64<<<dim3(M_ / 64, N_TOK / 64, BH), 256>>>(q, kl, sim, M_, ND, MD, MN);
    k_softmax8<<<BH * N_TOK / 8, 256>>>(sim);
    k_gemm64<3><<<dim3(1, N_TOK / 64, BH), 256>>>(sim, wm, oh, M_, D_, 0, M_, MN, MD, 0, 0.f, 0.f);

    // residual depthwise conv on v, += into out heads
    k_conv<<<dim3(N_TOK / 64, BH), 256>>>(v, w_res, oh);

    // final projection + bias
    k_final<<<dim3(4, 256), 256>>>(oh, w_out, b_out, out);
}

// round 10
// speedup vs baseline: 1.0557x; 1.0557x over previous
#include <cuda_runtime.h>
#include <math.h>

#define B_     4
#define N_TOK  8192
#define DIM_   512
#define H_     8
#define D_     64
#define M_     256
#define L_     32
#define BH     32
#define INNER3 1536
#define KS     33

// ---------------- scratch (device globals; no allocation allowed) ----------------
__device__ float g_q[BH * N_TOK * D_];
__device__ float g_k[BH * N_TOK * D_];
__device__ float g_v[BH * N_TOK * D_];
__device__ float g_qland[BH * M_ * D_];
__device__ float g_kland[BH * M_ * D_];
__device__ float g_attn2[BH * M_ * M_];
__device__ float g_zA[BH * M_ * M_];
__device__ float g_zB[BH * M_ * M_];
__device__ float g_xz[BH * M_ * M_];
__device__ float g_t1[BH * M_ * M_];
__device__ float g_t2[BH * M_ * M_];
__device__ float g_sim[67108864];          // [bh, 256, 8192] reused for sim3 then sim1
__device__ float g_a3v[BH * M_ * D_];
__device__ float g_w[BH * M_ * D_];
__device__ float g_outh[B_ * N_TOK * H_ * D_];   // [b, n, h, d]
__device__ unsigned g_scal[2];

// ---------------- zero-init (avoid memset nodes) ----------------
__global__ void k_zero(float* a3v, unsigned* scal) {
    int idx = blockIdx.x * 256 + threadIdx.x;
    if (idx < BH * M_ * D_) a3v[idx] = 0.f;
    if (idx < 2) scal[idx] = 0u;
}

// ---------------- QKV GEMM: [32768,512] @ [512,1536], scatter to q/k/v [b,h,n,d] ----------------
__global__ __launch_bounds__(256, 2)
void k_qkv(const float* __restrict__ X, const float* __restrict__ W,
           float* __restrict__ q, float* __restrict__ k, float* __restrict__ v) {
    __shared__ float As[8][132];
    __shared__ float Bs[8][128];
    const int tid  = threadIdx.x;
    const int row0 = blockIdx.y * 128;
    const int col0 = blockIdx.x * 128;
    const int tx = tid & 15, ty = tid >> 4;
    float acc[8][8];
#pragma unroll
    for (int i = 0; i < 8; i++)
#pragma unroll
        for (int j = 0; j < 8; j++) acc[i][j] = 0.f;

    const int a_row = tid >> 1, a_k = (tid & 1) * 4;
    const int b_k = tid >> 5, b_col = (tid & 31) * 4;
    const float* Ap = X + (row0 + a_row) * DIM_ + a_k;
    const float* Bp = W + b_k * INNER3 + col0 + b_col;

    for (int k0 = 0; k0 < DIM_; k0 += 8) {
        float4 a4 = *(const float4*)Ap; Ap += 8;
        float4 b4 = *(const float4*)Bp; Bp += 8 * INNER3;
        __syncthreads();
        As[a_k + 0][a_row] = a4.x; As[a_k + 1][a_row] = a4.y;
        As[a_k + 2][a_row] = a4.z; As[a_k + 3][a_row] = a4.w;
        *(float4*)&Bs[b_k][b_col] = b4;
        __syncthreads();
#pragma unroll
        for (int kk = 0; kk < 8; kk++) {
            float a[8], b[8];
#pragma unroll
            for (int i = 0; i < 8; i++) a[i] = As[kk][ty * 8 + i];
#pragma unroll
            for (int j = 0; j < 8; j++) b[j] = Bs[kk][tx * 8 + j];
#pragma unroll
            for (int i = 0; i < 8; i++)
#pragma unroll
                for (int j = 0; j < 8; j++) acc[i][j] = fmaf(a[i], b[j], acc[i][j]);
        }
    }
#pragma unroll
    for (int i = 0; i < 8; i++) {
        int r = row0 + ty * 8 + i;
        int bb = r >> 13, n = r & (N_TOK - 1);
#pragma unroll
        for (int j = 0; j < 8; j++) {
            int c = col0 + tx * 8 + j;
            int sect = c >> 9, cc = c & 511;
            int h = cc >> 6, d = cc & 63;
            int o = ((bb * H_ + h) * N_TOK + n) * D_ + d;
            float val = acc[i][j];
            if (sect == 0)      q[o] = val * 0.125f;   // dh^-0.5
            else if (sect == 1) k[o] = val;
            else                v[o] = val;
        }
    }
}

// ---------------- landmarks: mean over groups of 32 tokens ----------------
__global__ void k_land(const float* __restrict__ q, const float* __restrict__ k,
                       float* __restrict__ ql, float* __restrict__ kl) {
    int idx = blockIdx.x * 256 + threadIdx.x;
    if (idx >= BH * M_ * D_) return;
    int d = idx & 63, m = (idx >> 6) & 255, bh = idx >> 14;
    const float* qp = q + (bh * N_TOK + m * L_) * D_ + d;
    const float* kp = k + (bh * N_TOK + m * L_) * D_ + d;
    float sq = 0.f, sk = 0.f;
#pragma unroll
    for (int j = 0; j < L_; j++) { sq += qp[j * D_]; sk += kp[j * D_]; }
    ql[idx] = sq * (1.f / L_);
    kl[idx] = sk * (1.f / L_);
}

// ---------------- global max of row/col abs-sums of attn2 (all entries > 0) ----------------
__global__ void k_scal(const float* __restrict__ a2, unsigned* scal) {
    int bh = blockIdx.x, tid = threadIdx.x;
    const float* base = a2 + bh * M_ * M_;
    float cs = 0.f;                       // sums over axis -2
    for (int i = 0; i < M_; i++) cs += base[i * M_ + tid];
    float rs = 0.f;                       // sums over axis -1
    const float* rp = base + tid * M_;
    for (int j = 0; j < M_; j++) rs += rp[j];
    __shared__ float red[256];
    red[tid] = cs; __syncthreads();
    for (int o = 128; o; o >>= 1) { if (tid < o) red[tid] = fmaxf(red[tid], red[tid + o]); __syncthreads(); }
    if (tid == 0) atomicMax(&scal[0], __float_as_uint(red[0]));
    __syncthreads();
    red[tid] = rs; __syncthreads();
    for (int o = 128; o; o >>= 1) { if (tid < o) red[tid] = fmaxf(red[tid], red[tid + o]); __syncthreads(); }
    if (tid == 0) atomicMax(&scal[1], __float_as_uint(red[0]));
}

// ---------------- z0 = attn2^T / (max_rowsum * max_colsum) ----------------
__global__ void k_zinit(const float* __restrict__ a2, float* __restrict__ z, const unsigned* scal) {
    int idx = blockIdx.x * 256 + threadIdx.x;
    if (idx >= BH * M_ * M_) return;
    float sc = 1.f / (__uint_as_float(scal[0]) * __uint_as_float(scal[1]));
    int bh = idx >> 16, r = (idx >> 8) & 255, c = idx & 255;
    z[idx] = a2[(bh << 16) | (c << 8) | r] * sc;
}

// ---------------- batched pinv GEMM, 128x128 tile, 8x8/thread: C = s*(c*A - A@B) ----------------
// All matrices [256,256], row-major, batch stride 65536. Grid (2,2,BH).
__global__ __launch_bounds__(256, 2)
void k_gemm128(const float* __restrict__ A, const float* __restrict__ B, float* __restrict__ C,
               float cterm, float sterm) {
    const long long bs = (long long)blockIdx.z * (M_ * M_);
    A += bs; B += bs; C += bs;
    __shared__ float As[8][132];
    __shared__ float Bs[8][128];
    const int tid  = threadIdx.x;
    const int row0 = blockIdx.y * 128;
    const int col0 = blockIdx.x * 128;
    const int tx = tid & 15, ty = tid >> 4;
    float acc[8][8];
#pragma unroll
    for (int i = 0; i < 8; i++)
#pragma unroll
        for (int j = 0; j < 8; j++) acc[i][j] = 0.f;

    const int a_row = tid >> 1, a_k = (tid & 1) * 4;
    const int b_k = tid >> 5, b_col = (tid & 31) * 4;
    const float* Ap = A + (row0 + a_row) * M_ + a_k;
    const float* Bp = B + b_k * M_ + col0 + b_col;

    for (int k0 = 0; k0 < M_; k0 += 8) {
        float4 a4 = *(const float4*)Ap; Ap += 8;
        float4 b4 = *(const float4*)Bp; Bp += 8 * M_;
        __syncthreads();
        As[a_k + 0][a_row] = a4.x; As[a_k + 1][a_row] = a4.y;
        As[a_k + 2][a_row] = a4.z; As[a_k + 3][a_row] = a4.w;
        *(float4*)&Bs[b_k][b_col] = b4;
        __syncthreads();
#pragma unroll
        for (int kk = 0; kk < 8; kk++) {
            float a[8], b[8];
#pragma unroll
            for (int i = 0; i < 8; i++) a[i] = As[kk][ty * 8 + i];
#pragma unroll
            for (int j = 0; j < 8; j++) b[j] = Bs[kk][tx * 8 + j];
#pragma unroll
            for (int i = 0; i < 8; i++)
#pragma unroll
                for (int j = 0; j < 8; j++) acc[i][j] = fmaf(a[i], b[j], acc[i][j]);
        }
    }
#pragma unroll
    for (int i = 0; i < 8; i++) {
        int row = row0 + ty * 8 + i;
#pragma unroll
        for (int j = 0; j < 8; j++) {
            int col = col0 + tx * 8 + j;
            float ae = A[row * M_ + col];
            C[row * M_ + col] = sterm * (cterm * ae - acc[i][j]);
        }
    }
}

// ---------------- generic batched 64x64-tile NN GEMM ----------------
// MODE 1: C = A@B
// MODE 2: split-K, atomicAdd(C, A@B)   (blockIdx.z = bh*8 + kchunk)
// MODE 3: C = A@B scattered to g_outh layout [b,n,h,d] (batch = bh)
template <int MODE>
__global__ __launch_bounds__(256)
void k_gemm64(const float* __restrict__ A, const float* __restrict__ B, float* __restrict__ C,
              int lda, int ldb, int ldc, int Ksz,
              long long sA, long long sB, long long sC) {
    int bz = blockIdx.z;
    int batch = (MODE == 2) ? (bz >> 3) : bz;
    int kc    = (MODE == 2) ? (bz & 7) : 0;
    A += (long long)batch * sA; B += (long long)batch * sB; C += (long long)batch * sC;
    int m0 = blockIdx.y * 64, n0 = blockIdx.x * 64;
    __shared__ float As[16][68];
    __shared__ float Bs[16][64];
    int tid = threadIdx.x;
    int a_m = tid >> 2, a_k = (tid & 3) * 4;
    int b_k = tid >> 4, b_n = (tid & 15) * 4;
    int tm = tid >> 4, tn = tid & 15;
    float acc[4][4];
#pragma unroll
    for (int i = 0; i < 4; i++)
#pragma unroll
        for (int j = 0; j < 4; j++) acc[i][j] = 0.f;

    int koff = kc * Ksz;
    const float* Ap = A + (m0 + a_m) * lda + koff + a_k;
    const float* Bp = B + (long long)(koff + b_k) * ldb + n0 + b_n;
    for (int k0 = 0; k0 < Ksz; k0 += 16) {
        float4 a4 = *(const float4*)Ap; Ap += 16;
        float4 b4 = *(const float4*)Bp; Bp += 16 * (long long)ldb;
        __syncthreads();
        As[a_k + 0][a_m] = a4.x; As[a_k + 1][a_m] = a4.y;
        As[a_k + 2][a_m] = a4.z; As[a_k + 3][a_m] = a4.w;
        *(float4*)&Bs[b_k][b_n] = b4;
        __syncthreads();
#pragma unroll
        for (int kk = 0; kk < 16; kk++) {
            float4 a = *(const float4*)&As[kk][tm * 4];
            float4 b = *(const float4*)&Bs[kk][tn * 4];
            acc[0][0] = fmaf(a.x, b.x, acc[0][0]); acc[0][1] = fmaf(a.x, b.y, acc[0][1]);
            acc[0][2] = fmaf(a.x, b.z, acc[0][2]); acc[0][3] = fmaf(a.x, b.w, acc[0][3]);
            acc[1][0] = fmaf(a.y, b.x, acc[1][0]); acc[1][1] = fmaf(a.y, b.y, acc[1][1]);
            acc[1][2] = fmaf(a.y, b.z, acc[1][2]); acc[1][3] = fmaf(a.y, b.w, acc[1][3]);
            acc[2][0] = fmaf(a.z, b.x, acc[2][0]); acc[2][1] = fmaf(a.z, b.y, acc[2][1]);
            acc[2][2] = fmaf(a.z, b.z, acc[2][2]); acc[2][3] = fmaf(a.z, b.w, acc[2][3]);
            acc[3][0] = fmaf(a.w, b.x, acc[3][0]); acc[3][1] = fmaf(a.w, b.y, acc[3][1]);
            acc[3][2] = fmaf(a.w, b.z, acc[3][2]); acc[3][3] = fmaf(a.w, b.w, acc[3][3]);
        }
    }
#pragma unroll
    for (int i = 0; i < 4; i++) {
        int row = m0 + tm * 4 + i;
#pragma unroll
        for (int j = 0; j < 4; j++) {
            int col = n0 + tn * 4 + j;
            if (MODE == 1) {
                C[row * ldc + col] = acc[i][j];
            } else if (MODE == 2) {
                atomicAdd(&C[row * ldc + col], acc[i][j]);
            } else {
                int b = batch >> 3, h = batch & 7;
                C[((b * N_TOK + row) * H_ + h) * D_ + col] = acc[i][j];
            }
        }
    }
}

// ---------------- NT GEMM, K=64 resident: C[M,N] = A[M,64] . B[N,64]^T ----------------
__global__ __launch_bounds__(256)
void k_nt64(const float* __restrict__ A, const float* __restrict__ B, float* __restrict__ C,
            int Nc, long long sA, long long sB, long long sC) {
    int bh = blockIdx.z;
    A += (long long)bh * sA; B += (long long)bh * sB; C += (long long)bh * sC;
    int n0 = blockIdx.x * 64, m0 = blockIdx.y * 64;
    __shared__ float As[64][68];
    __shared__ float Bs[64][68];
    int tid = threadIdx.x;
    int lm = tid >> 2, lk = (tid & 3) * 4;
    const float* Ap = A + (m0 + lm) * 64 + lk;
    const float* Bp = B + (n0 + lm) * 64 + lk;
#pragma unroll
    for (int qq = 0; qq < 4; qq++) {
        float4 a4 = *(const float4*)(Ap + qq * 16);
        int kb = lk + 16 * qq;
        As[kb + 0][lm] = a4.x; As[kb + 1][lm] = a4.y; As[kb + 2][lm] = a4.z; As[kb + 3][lm] = a4.w;
        float4 b4 = *(const float4*)(Bp + qq * 16);
        Bs[kb + 0][lm] = b4.x; Bs[kb + 1][lm] = b4.y; Bs[kb + 2][lm] = b4.z; Bs[kb + 3][lm] = b4.w;
    }
    __syncthreads();
    int tm = tid >> 4, tn = tid & 15;
    float acc[4][4];
#pragma unroll
    for (int i = 0; i < 4; i++)
#pragma unroll
        for (int j = 0; j < 4; j++) acc[i][j] = 0.f;
#pragma unroll 8
    for (int kk = 0; kk < 64; kk++) {
        float4 a = *(const float4*)&As[kk][tm * 4];
        float4 b = *(const float4*)&Bs[kk][tn * 4];
        acc[0][0] = fmaf(a.x, b.x, acc[0][0]); acc[0][1] = fmaf(a.x, b.y, acc[0][1]);
        acc[0][2] = fmaf(a.x, b.z, acc[0][2]); acc[0][3] = fmaf(a.x, b.w, acc[0][3]);
        acc[1][0] = fmaf(a.y, b.x, acc[1][0]); acc[1][1] = fmaf(a.y, b.y, acc[1][1]);
        acc[1][2] = fmaf(a.y, b.z, acc[1][2]); acc[1][3] = fmaf(a.y, b.w, acc[1][3]);
        acc[2][0] = fmaf(a.z, b.x, acc[2][0]); acc[2][1] = fmaf(a.z, b.y, acc[2][1]);
        acc[2][2] = fmaf(a.z, b.z, acc[2][2]); acc[2][3] = fmaf(a.z, b.w, acc[2][3]);
        acc[3][0] = fmaf(a.w, b.x, acc[3][0]); acc[3][1] = fmaf(a.w, b.y, acc[3][1]);
        acc[3][2] = fmaf(a.w, b.z, acc[3][2]); acc[3][3] = fmaf(a.w, b.w, acc[3][3]);
    }
#pragma unroll
    for (int i = 0; i < 4; i++)
#pragma unroll
        for (int j = 0; j < 4; j++)
            C[(m0 + tm * 4 + i) * Nc + n0 + tn * 4 + j] = acc[i][j];
}

// ---------------- softmax over rows of length 8192 (single pass, regs) ----------------
__global__ void k_softmax_wide(float* __restrict__ data) {
    float* row = data + (size_t)blockIdx.x * N_TOK;
    int t = threadIdx.x;
    float v[32];
    float m = -1e30f;
#pragma unroll
    for (int i = 0; i < 32; i++) { v[i] = row[t + 256 * i]; m = fmaxf(m, v[i]); }
    __shared__ float red[256];
    red[t] = m; __syncthreads();
    for (int o = 128; o; o >>= 1) { if (t < o) red[t] = fmaxf(red[t], red[t + o]); __syncthreads(); }
    m = red[0]; __syncthreads();
    float s = 0.f;
#pragma unroll
    for (int i = 0; i < 32; i++) { v[i] = expf(v[i] - m); s += v[i]; }
    red[t] = s; __syncthreads();
    for (int o = 128; o; o >>= 1) { if (t < o) red[t] += red[t + o]; __syncthreads(); }
    float r = 1.f / red[0];
#pragma unroll
    for (int i = 0; i < 32; i++) row[t + 256 * i] = v[i] * r;
}

// ---------------- softmax over rows of length 256 (warp per row, 8 rows/CTA) ----------------
__global__ void k_softmax8(float* __restrict__ data) {
    int warp = threadIdx.x >> 5, lane = threadIdx.x & 31;
    float* row = data + ((size_t)blockIdx.x * 8 + warp) * M_;
    float v[8];
    float m = -1e30f;
#pragma unroll
    for (int i = 0; i < 8; i++) { v[i] = row[lane + 32 * i]; m = fmaxf(m, v[i]); }
#pragma unroll
    for (int o = 16; o; o >>= 1) m = fmaxf(m, __shfl_xor_sync(0xffffffffu, m, o));
    float s = 0.f;
#pragma unroll
    for (int i = 0; i < 8; i++) { v[i] = expf(v[i] - m); s += v[i]; }
#pragma unroll
    for (int o = 16; o; o >>= 1) s += __shfl_xor_sync(0xffffffffu, s, o);
    float r = 1.f / s;
#pragma unroll
    for (int i = 0; i < 8; i++) row[lane + 32 * i] = v[i] * r;
}

// ---------------- depthwise residual conv over sequence axis, += into g_outh ----------------
__global__ void k_conv(const float* __restrict__ v, const float* __restrict__ wres,
                       float* __restrict__ oh) {
    int n0 = blockIdx.x * 64, bh = blockIdx.y, tid = threadIdx.x;
    int b = bh >> 3, h = bh & 7;
    __shared__ float vs[96][64];
    __shared__ float ws[KS];
    if (tid < KS) ws[tid] = wres[h * KS + tid];
    for (int l = tid; l < 96 * 64; l += 256) {
        int row = l >> 6, d = l & 63;
        int n = n0 + row - 16;
        vs[row][d] = (n >= 0 && n < N_TOK) ? v[(bh * N_TOK + n) * D_ + d] : 0.f;
    }
    __syncthreads();
    for (int o = tid; o < 64 * 64; o += 256) {
        int r = o >> 6, d = o & 63;
        float acc = 0.f;
#pragma unroll
        for (int t = 0; t < KS; t++) acc = fmaf(ws[t], vs[r + t][d], acc);
        int idx = ((b * N_TOK + n0 + r) * H_ + h) * D_ + d;
        oh[idx] += acc;
    }
}

// ---------------- final projection: [32768,512] @ [512,512] + bias -> d_out ----------------
__global__ __launch_bounds__(256, 2)
void k_final(const float* __restrict__ A, const float* __restrict__ W,
             const float* __restrict__ bias, float* __restrict__ C) {
    __shared__ float As[8][132];
    __shared__ float Bs[8][128];
    const int tid = threadIdx.x;
    const int row0 = blockIdx.y * 128;
    const int col0 = blockIdx.x * 128;
    const int tx = tid & 15, ty = tid >> 4;
    float acc[8][8];
#pragma unroll
    for (int i = 0; i < 8; i++)
#pragma unroll
        for (int j = 0; j < 8; j++) acc[i][j] = 0.f;
    const int a_row = tid >> 1, a_k = (tid & 1) * 4;
    const int b_k = tid >> 5, b_col = (tid & 31) * 4;
    const float* Ap = A + (row0 + a_row) * DIM_ + a_k;
    const float* Bp = W + b_k * DIM_ + col0 + b_col;
    for (int k0 = 0; k0 < DIM_; k0 += 8) {
        float4 a4 = *(const float4*)Ap; Ap += 8;
        float4 b4 = *(const float4*)Bp; Bp += 8 * DIM_;
        __syncthreads();
        As[a_k + 0][a_row] = a4.x; As[a_k + 1][a_row] = a4.y;
        As[a_k + 2][a_row] = a4.z; As[a_k + 3][a_row] = a4.w;
        *(float4*)&Bs[b_k][b_col] = b4;
        __syncthreads();
#pragma unroll
        for (int kk = 0; kk < 8; kk++) {
            float a[8], b[8];
#pragma unroll
            for (int i = 0; i < 8; i++) a[i] = As[kk][ty * 8 + i];
#pragma unroll
            for (int j = 0; j < 8; j++) b[j] = Bs[kk][tx * 8 + j];
#pragma unroll
            for (int i = 0; i < 8; i++)
#pragma unroll
                for (int j = 0; j < 8; j++) acc[i][j] = fmaf(a[i], b[j], acc[i][j]);
        }
    }
#pragma unroll
    for (int i = 0; i < 8; i++) {
        int r = row0 + ty * 8 + i;
#pragma unroll
        for (int j = 0; j < 8; j++) {
            int c = col0 + tx * 8 + j;
            C[(size_t)r * DIM_ + c] = acc[i][j] + bias[c];
        }
    }
}

// ---------------- driver ----------------
extern "C" void kernel_launch(void* const* d_in, const int* in_sizes, int n_in,
                              void* d_out, int out_size) {
    const float* x     = (const float*)d_in[0];
    const float* w_qkv = (const float*)d_in[1];
    const float* w_out = (const float*)d_in[2];
    const float* b_out = (const float*)d_in[3];
    const float* w_res = (const float*)d_in[4];
    float* out = (float*)d_out;

    float *q, *k, *v, *ql, *kl, *a2, *zA, *zB, *xz, *t1, *t2, *sim, *a3v, *wm, *oh;
    unsigned* scal;
    cudaGetSymbolAddress((void**)&q, g_q);
    cudaGetSymbolAddress((void**)&k, g_k);
    cudaGetSymbolAddress((void**)&v, g_v);
    cudaGetSymbolAddress((void**)&ql, g_qland);
    cudaGetSymbolAddress((void**)&kl, g_kland);
    cudaGetSymbolAddress((void**)&a2, g_attn2);
    cudaGetSymbolAddress((void**)&zA, g_zA);
    cudaGetSymbolAddress((void**)&zB, g_zB);
    cudaGetSymbolAddress((void**)&xz, g_xz);
    cudaGetSymbolAddress((void**)&t1, g_t1);
    cudaGetSymbolAddress((void**)&t2, g_t2);
    cudaGetSymbolAddress((void**)&sim, g_sim);
    cudaGetSymbolAddress((void**)&a3v, g_a3v);
    cudaGetSymbolAddress((void**)&wm, g_w);
    cudaGetSymbolAddress((void**)&oh, g_outh);
    cudaGetSymbolAddress((void**)&scal, g_scal);

    const long long MM = (long long)M_ * M_;        // 65536
    const long long MD = (long long)M_ * D_;        // 16384
    const long long ND = (long long)N_TOK * D_;     // 524288
    const long long MN = (long long)M_ * N_TOK;     // 2097152

    k_zero<<<(BH * M_ * D_ + 255) / 256, 256>>>(a3v, scal);

    // qkv projection + head split + q scale
    k_qkv<<<dim3(12, 256), 256>>>(x, w_qkv, q, k, v);
    // landmarks
    k_land<<<(BH * M_ * D_ + 255) / 256, 256>>>(q, k, ql, kl);

    // attn2 = softmax(q_land . k_land^T): tiled NT GEMM + warp-per-row softmax
    k_nt64<<<dim3(M_ / 64, M_ / 64, BH), 256>>>(ql, kl, a2, M_, MD, MD, MM);
    k_softmax8<<<BH * M_ / 8, 256>>>(a2);
    k_scal<<<BH, 256>>>(a2, scal);
    k_zinit<<<(BH * M_ * M_ + 255) / 256, 256>>>(a2, zA, scal);

    // Newton–Schulz pinv, 6 iterations, ping-pong z, 128x128-tile GEMMs
    float* zin = zA; float* zout = zB;
    for (int it = 0; it < 6; it++) {
        k_gemm128<<<dim3(2, 2, BH), 256>>>(a2, zin, xz, 0.f, -1.f);
        k_gemm128<<<dim3(2, 2, BH), 256>>>(xz, xz, t1, 7.f, 1.f);
        k_gemm128<<<dim3(2, 2, BH), 256>>>(xz, t1, t2, 15.f, 1.f);
        k_gemm128<<<dim3(2, 2, BH), 256>>>(zin, t2, zout, 13.f, 0.25f);
        float* tmp = zin; zin = zout; zout = tmp;
    }
    // zin now holds attn2_inv

    // attn3 = softmax(q_land . k^T)  [bh,256,8192], then attn3 @ v (split-K=8)
    k_nt64<<<dim3(N_TOK / 64, M_ / 64, BH), 256>>>(ql, k, sim, N_TOK, MD, ND, MN);
    k_softmax_wide<<<BH * M_, 256>>>(sim);
    k_gemm64<2><<<dim3(1, 4, BH * 8), 256>>>(sim, v, a3v, N_TOK, D_, D_, 1024, MN, ND, MD);

    // W = attn2_inv @ (attn3 @ v)
    k_gemm64<1><<<dim3(1, 4, BH), 256>>>(zin, a3v, wm, M_, D_, D_, M_, MM, MD, MD);

    // attn1 = softmax(q . k_land^T)  [bh,8192,256], then out = attn1 @ W  -> [b,n,h,d]
    k_nt64<<<dim3(M_ / 64, N_TOK / 64, BH), 256>>>(q, kl, sim, M_, ND, MD, MN);
    k_softmax8<<<BH * N_TOK / 8, 256>>>(sim);
    k_gemm64<3><<<dim3(1, N_TOK / 64, BH), 256>>>(sim, wm, oh, M_, D_, 0, M_, MN, MD, 0);

    // residual depthwise conv on v, += into out heads
    k_conv<<<dim3(N_TOK / 64, BH), 256>>>(v, w_res, oh);

    // final projection + bias
    k_final<<<dim3(4, 256), 256>>>(oh, w_out, b_out, out);
}